// round 5
// baseline (speedup 1.0000x reference)
#include <cuda_runtime.h>

// CoupledClustersLossV2 — single-kernel, single-pass, HBM-bound.
// embeddings: [256 cls][2 pos/neg][32 samples][2048] fp32 = 128 MB.
// ||x - a||^2 = ||x||^2 - (x·s)/16 + ||s||^2/1024  with s = sum(pos rows);
// every term decomposes over D-chunks, so each class is split across 4 CTAs
// (512 columns each) and partial row-sums (pn, tp, nn, tn) add up.
// All x/y data is consumed straight from LDG registers; SMEM is used only for
// the cross-warp column-sum s (4.5 KB / chunk). Per-class combine + final mean
// are fused via epoch counters (replay-safe: finisher = old % N == N-1).

#define NCLS    256
#define NS      32
#define DIM     2048
#define NPART   4
#define DPART   (DIM / NPART)     // 512
#define CHUNK   128
#define NCH     (DPART / CHUNK)   // 4
#define THREADS 256
#define MARGIN  0.3f

// quantities: 0=||pos||^2, 1=pos·s, 2=||neg||^2, 3=neg·s   (per sample row)
__device__ float        g_scratch[NCLS][NPART][4][NS];
__device__ unsigned int g_done[NCLS];        // epoch counters (never reset)
__device__ float        g_class_loss[NCLS];
__device__ unsigned int g_cls_done;          // epoch counter (never reset)

__device__ __forceinline__ float dot4(float4 a, float4 b) {
    return fmaf(a.x, b.x, fmaf(a.y, b.y, fmaf(a.z, b.z, a.w * b.w)));
}
__device__ __forceinline__ float wsum(float v) {
#pragma unroll
    for (int o = 16; o > 0; o >>= 1) v += __shfl_xor_sync(0xffffffffu, v, o);
    return v;
}

__global__ __launch_bounds__(THREADS, 2)
void ccl_kernel(const float* __restrict__ emb, float* __restrict__ out)
{
    __shared__ float spart[8][CHUNK];   // per-warp column-sum partials (4 KB)
    __shared__ float s_sh[CHUNK];       // reduced column sums (512 B)
    __shared__ int   sflag;

    const int cls  = blockIdx.x >> 2;
    const int part = blockIdx.x & 3;
    const int tid  = threadIdx.x;
    const int warp = tid >> 5;
    const int lane = tid & 31;

    const float* base = emb + (size_t)cls * (size_t)(2 * NS * DIM)
                            + (size_t)part * DPART;

    // Warp w owns sample rows {w, w+8, w+16, w+24}; lane owns 4 consecutive cols.
    const float4* pp[4];
    const float4* np[4];
#pragma unroll
    for (int it = 0; it < 4; ++it) {
        const int row = warp + it * 8;
        pp[it] = (const float4*)(base + (size_t)row        * DIM) + lane;
        np[it] = (const float4*)(base + (size_t)(NS + row) * DIM) + lane;
    }

    // Register double-buffered tiles: 32 rows x 128 cols, pos and neg.
    float4 pb[2][4], nb[2][4];
#pragma unroll
    for (int it = 0; it < 4; ++it) { pb[0][it] = pp[it][0]; nb[0][it] = np[it][0]; }

    float pnL[4] = {0.f,0.f,0.f,0.f};
    float nnL[4] = {0.f,0.f,0.f,0.f};
    float tpL[4] = {0.f,0.f,0.f,0.f};
    float tnL[4] = {0.f,0.f,0.f,0.f};

#pragma unroll
    for (int k = 0; k < NCH; ++k) {
        const int cur = k & 1, nxt = cur ^ 1;

        // Prefetch next chunk (LDGs fly while we compute below).
        if (k + 1 < NCH) {
#pragma unroll
            for (int it = 0; it < 4; ++it) {
                pb[nxt][it] = pp[it][(k + 1) * (CHUNK / 4)];
                nb[nxt][it] = np[it][(k + 1) * (CHUNK / 4)];
            }
        }

        // Per-warp partial column sums of the pos chunk (4 of the 32 rows).
        float4 sp;
        sp.x = (pb[cur][0].x + pb[cur][1].x) + (pb[cur][2].x + pb[cur][3].x);
        sp.y = (pb[cur][0].y + pb[cur][1].y) + (pb[cur][2].y + pb[cur][3].y);
        sp.z = (pb[cur][0].z + pb[cur][1].z) + (pb[cur][2].z + pb[cur][3].z);
        sp.w = (pb[cur][0].w + pb[cur][1].w) + (pb[cur][2].w + pb[cur][3].w);
        *(float4*)&spart[warp][lane * 4] = sp;

        // Row norms straight from registers.
#pragma unroll
        for (int it = 0; it < 4; ++it) {
            pnL[it] += dot4(pb[cur][it], pb[cur][it]);
            nnL[it] += dot4(nb[cur][it], nb[cur][it]);
        }
        __syncthreads();

        // Reduce column sums across the 8 warps.
        if (tid < CHUNK) {
            float s = 0.f;
#pragma unroll
            for (int w = 0; w < 8; ++w) s += spart[w][tid];
            s_sh[tid] = s;
        }
        __syncthreads();

        // Dots with s straight from registers.
        const float4 sc = *(const float4*)&s_sh[lane * 4];
#pragma unroll
        for (int it = 0; it < 4; ++it) {
            tpL[it] += dot4(pb[cur][it], sc);
            tnL[it] += dot4(nb[cur][it], sc);
        }
        // No extra barrier: next iter's spart STS / s_sh write are fenced by
        // this iter's two syncs (writes happen only after all reads complete).
    }

    // Per-row warp reductions -> per-part scratch (fixed order, deterministic).
#pragma unroll
    for (int it = 0; it < 4; ++it) {
        const float a = wsum(pnL[it]);
        const float b = wsum(tpL[it]);
        const float c = wsum(nnL[it]);
        const float d = wsum(tnL[it]);
        if (lane == 0) {
            const int row = warp + it * 8;
            g_scratch[cls][part][0][row] = a;
            g_scratch[cls][part][1][row] = b;
            g_scratch[cls][part][2][row] = c;
            g_scratch[cls][part][3][row] = d;
        }
    }
    __threadfence();
    __syncthreads();
    if (tid == 0) {
        const unsigned old = atomicAdd(&g_done[cls], 1u);
        sflag = ((old & (NPART - 1u)) == (NPART - 1u)) ? 1 : 0;
    }
    __syncthreads();
    if (sflag == 0 || warp != 0) return;

    // ---- per-class finisher (warp 0 of the last-arriving CTA) ----
    __threadfence();
    float pn = 0.f, tp = 0.f, nn = 0.f, tn = 0.f;
#pragma unroll
    for (int p = 0; p < NPART; ++p) {          // fixed order -> deterministic
        pn += __ldcg(&g_scratch[cls][p][0][lane]);
        tp += __ldcg(&g_scratch[cls][p][1][lane]);
        nn += __ldcg(&g_scratch[cls][p][2][lane]);
        tn += __ldcg(&g_scratch[cls][p][3][lane]);
    }
    const float ssum  = wsum(tp);              // ||s||^2 = sum_i pos_i . s
    const float anorm = ssum * (1.0f / 1024.0f);
    const float ap2   = pn - tp * (1.0f / 16.0f) + anorm;
    const float nd2   = nn - tn * (1.0f / 16.0f) + anorm;

    float mn = nd2;
#pragma unroll
    for (int o = 16; o > 0; o >>= 1)
        mn = fminf(mn, __shfl_xor_sync(0xffffffffu, mn, o));
    const float an = sqrtf(fmaxf(mn, 0.f));

    float t = fmaxf(sqrtf(fmaxf(ap2, 0.f)) - an + MARGIN, 0.f);
    const float term = wsum(t * t);

    unsigned old2 = 0;
    if (lane == 0) {
        g_class_loss[cls] = term;
        __threadfence();
        old2 = atomicAdd(&g_cls_done, 1u);
    }
    old2 = __shfl_sync(0xffffffffu, old2, 0);
    if ((old2 & (NCLS - 1u)) != (NCLS - 1u)) return;

    // ---- global finisher: fixed-order mean over 256 class losses ----
    __threadfence();
    float v = 0.f;
#pragma unroll
    for (int c = 0; c < NCLS / 32; ++c)
        v += __ldcg(&g_class_loss[c * 32 + lane]);
    v = wsum(v);
    if (lane == 0) out[0] = v * (1.0f / (float)NCLS);
}

extern "C" void kernel_launch(void* const* d_in, const int* in_sizes, int n_in,
                              void* d_out, int out_size)
{
    (void)in_sizes; (void)n_in; (void)out_size;
    const float* emb = (const float*)d_in[0];   // [16384, 2048] fp32
    // d_in[1] (target) is unused by the reference computation.
    ccl_kernel<<<NCLS * NPART, THREADS>>>(emb, (float*)d_out);
}